// round 17
// baseline (speedup 1.0000x reference)
#include <cuda_runtime.h>
#include <math.h>
#include <stdint.h>

#define H 192
#define MAXZ 8192
#define EPSLN 1e-5f

// ===== device scratch (static, no runtime allocation) =====
__device__ float g_Wt[8 * H * H];   // transposed: L layer-W's + W1a/W1b/W1c
__device__ float g_P1[MAXZ * H];    // includes +v fold
__device__ float g_P2[MAXZ * H];
__device__ float g_u[H];
__device__ float g_v[H];

// ---------------------------------------------------------------------------
// Kernel 0: weight transpose (64x64 tiles) + u/v build.
//   z <  L+3           : transpose matrix z into g_Wt[z][k][c]
//   z == L+3 (x=y=0)   : u = W1c@dW ; v = W1c@dB + b1   (reads original W1)
// ---------------------------------------------------------------------------
__global__ __launch_bounds__(256)
void transpose_kernel(const float* __restrict__ lW, const float* __restrict__ hW1,
                      const float* __restrict__ dW, const float* __restrict__ dB,
                      const float* __restrict__ b1, int L)
{
    const int mat = blockIdx.z;
    const int tid = threadIdx.x;

    if (mat == L + 3) {
        if (blockIdx.x || blockIdx.y) return;
        __shared__ float sw[H], sb[H];
        if (tid < H) { sw[tid] = dW[tid]; sb[tid] = dB[tid]; }
        __syncthreads();
        if (tid < H) {
            const float* wr = hW1 + (size_t)tid * 3 * H + 2 * H;
            float au = 0.f, av = 0.f;
#pragma unroll 4
            for (int k = 0; k < H; k++) {
                float w = wr[k];
                au = fmaf(w, sw[k], au);
                av = fmaf(w, sb[k], av);
            }
            g_u[tid] = au;
            g_v[tid] = av + b1[tid];
        }
        return;
    }

    __shared__ float tile[64][65];
    const float* src; int rs;
    if (mat < L) { src = lW + (size_t)mat * H * H; rs = H; }
    else         { src = hW1 + (size_t)(mat - L) * H; rs = 3 * H; }
    float* dst = g_Wt + (size_t)mat * H * H;

    const int k0 = blockIdx.x * 64, c0 = blockIdx.y * 64;
    const int tx = tid & 63, ty = tid >> 6;   // 64 x 4
#pragma unroll
    for (int i = 0; i < 64; i += 4)
        tile[ty + i][tx] = src[(size_t)(c0 + ty + i) * rs + k0 + tx];
    __syncthreads();
#pragma unroll
    for (int i = 0; i < 64; i += 4)
        dst[(size_t)(k0 + ty + i) * H + c0 + tx] = tile[tx][ty + i];
}

// ---------------------------------------------------------------------------
// Kernel A: tower for z-row bx + P1'/P2 rows (coalesced Wt reads).
// P1' = W1a @ tower(emb[z]) + v  (v folded here; g_v ready from kernel 0).
// 192 threads, thread = one hidden column.
// ---------------------------------------------------------------------------
__global__ __launch_bounds__(192)
void prep_kernel(const float* __restrict__ emb,
                 const float* __restrict__ layer_b,
                 const float* __restrict__ layer_g,
                 const float* __restrict__ layer_bt,
                 int L)
{
    __shared__ float hs[H];
    __shared__ float red_s[6], red_q[6];

    const int t = threadIdx.x;
    const int bx = blockIdx.x;
    const int wid = t >> 5, lane = t & 31;

    hs[t] = emb[(size_t)bx * H + t];
    __syncthreads();

    for (int l = 0; l < L; l++) {
        const float* wt = g_Wt + (size_t)l * H * H + t;
        float a0 = 0.f, a1 = 0.f, a2 = 0.f, a3 = 0.f;
#pragma unroll
        for (int k = 0; k < H; k += 4) {
            a0 = fmaf(wt[(size_t)(k    ) * H], hs[k    ], a0);
            a1 = fmaf(wt[(size_t)(k + 1) * H], hs[k + 1], a1);
            a2 = fmaf(wt[(size_t)(k + 2) * H], hs[k + 2], a2);
            a3 = fmaf(wt[(size_t)(k + 3) * H], hs[k + 3], a3);
        }
        float y = (a0 + a1) + (a2 + a3) + layer_b[l * H + t];

        float s = y, q = y * y;
#pragma unroll
        for (int o = 16; o > 0; o >>= 1) {
            s += __shfl_xor_sync(0xffffffffu, s, o);
            q += __shfl_xor_sync(0xffffffffu, q, o);
        }
        if (lane == 0) { red_s[wid] = s; red_q[wid] = q; }
        __syncthreads();
        float S = red_s[0] + red_s[1] + red_s[2] + red_s[3] + red_s[4] + red_s[5];
        float Q = red_q[0] + red_q[1] + red_q[2] + red_q[3] + red_q[4] + red_q[5];
        float mu = S * (1.f / 192.f);
        float var = Q * (1.f / 192.f) - mu * mu;
        float rstd = rsqrtf(fmaxf(var, 0.f) + EPSLN);

        float v = fmaxf((y - mu) * rstd * layer_g[l * H + t] + layer_bt[l * H + t], 0.f);
        float hnew = hs[t] + v;
        __syncthreads();
        hs[t] = hnew;
        __syncthreads();
    }

    // P1' (with +v fold) and P2 from W1a^T / W1b^T (coalesced)
    {
        const float* wa = g_Wt + (size_t)L * H * H + t;
        const float* wb = g_Wt + (size_t)(L + 1) * H * H + t;
        float p1a = 0.f, p1b = 0.f, p2a = 0.f, p2b = 0.f;
#pragma unroll
        for (int k = 0; k < H; k += 2) {
            float h0 = hs[k], h1 = hs[k + 1];
            p1a = fmaf(wa[(size_t)k * H],       h0, p1a);
            p1b = fmaf(wa[(size_t)(k + 1) * H], h1, p1b);
            p2a = fmaf(wb[(size_t)k * H],       h0, p2a);
            p2b = fmaf(wb[(size_t)(k + 1) * H], h1, p2b);
        }
        g_P1[(size_t)bx * H + t] = p1a + p1b + g_v[t];
        g_P2[(size_t)bx * H + t] = p2a + p2b;
    }
}

// ---------------------------------------------------------------------------
// Kernel B: final. TWO molecules per phase-2 iteration (half-warp each).
// Lane (l&15) owns 12 cols as 3 float4: c = (l&15)*4 + 64*seg.
// out[m] = relu(P1'[z1] + P2[z2] + d*u) . W2 + b2
// ---------------------------------------------------------------------------
__global__ __launch_bounds__(256, 4)
void final_kernel(const int* __restrict__ z, const float* __restrict__ pos,
                  const float* __restrict__ W2, const float* __restrict__ b2,
                  float* __restrict__ out, int B, int apm)
{
    const int tid = threadIdx.x;
    const int wid = tid >> 5, lane = tid & 31;
    const int lane16 = lane & 15, half = lane >> 4;

    float4 uu[3], ww[3];
#pragma unroll
    for (int seg = 0; seg < 3; seg++) {
        int c = lane16 * 4 + 64 * seg;
        uu[seg] = *(const float4*)(g_u + c);
        ww[seg] = *(const float4*)(W2 + c);
    }
    const float b2v = b2[0];
    const char* P1b = (const char*)g_P1;
    const char* P2b = (const char*)g_P2;
    const bool has2 = (apm > 1);

    const int warpsTotal = gridDim.x * 8;
    for (int base = (blockIdx.x * 8 + wid) * 32; base < B; base += warpsTotal * 32) {
        const int cnt = min(32, B - base);

        // ---- phase 1: lane-parallel scalars (lane = molecule) ----
        int zz = 0;
        float d = 0.f;
        if (lane < cnt) {
            const int m = base + lane;
            const int f = m * apm;
            if (has2) {
                int2 zp = *(const int2*)(z + f);
                zz = zp.x | (zp.y << 16);
                const float* pp = pos + 3 * f;
                float4 p0 = *(const float4*)pp;        // x1 y1 z1 x2
                float2 p1 = *(const float2*)(pp + 4);  // y2 z2
                float ax = p0.x - p0.w;
                float ay = p0.y - p1.x;
                float az = p0.z - p1.y;
                d = sqrtf(ax * ax + ay * ay + az * az + 1e-12f);
            } else {
                int zv = z[f];
                zz = zv | (zv << 16);
            }
        }

        // ---- phase 2: two molecules per iteration ----
        for (int j = 0; j < cnt; j += 2) {
            int srcL = j + half;
            if (srcL >= cnt) srcL = j;              // odd tail: high half duplicates
            const int   zzj = __shfl_sync(0xffffffffu, zz, srcL);
            const float dj  = __shfl_sync(0xffffffffu, d, srcL);
            const uint32_t o1 = (uint32_t)(zzj & 0xffff) * (H * 4u) + lane16 * 16u;
            const uint32_t o2 = (uint32_t)(zzj >> 16)    * (H * 4u) + lane16 * 16u;
            float4 a0 = __ldg((const float4*)(P1b + o1));
            float4 a1 = __ldg((const float4*)(P1b + o1 + 256));
            float4 a2 = __ldg((const float4*)(P1b + o1 + 512));
            float4 c0 = __ldg((const float4*)(P2b + o2));
            float4 c1 = __ldg((const float4*)(P2b + o2 + 256));
            float4 c2 = __ldg((const float4*)(P2b + o2 + 512));

            float s = 0.f;
            {
                float x;
                x = fmaf(dj, uu[0].x, a0.x + c0.x); s  = fmaxf(x, 0.f) * ww[0].x;
                x = fmaf(dj, uu[0].y, a0.y + c0.y); s  = fmaf(fmaxf(x, 0.f), ww[0].y, s);
                x = fmaf(dj, uu[0].z, a0.z + c0.z); s  = fmaf(fmaxf(x, 0.f), ww[0].z, s);
                x = fmaf(dj, uu[0].w, a0.w + c0.w); s  = fmaf(fmaxf(x, 0.f), ww[0].w, s);
                x = fmaf(dj, uu[1].x, a1.x + c1.x); s  = fmaf(fmaxf(x, 0.f), ww[1].x, s);
                x = fmaf(dj, uu[1].y, a1.y + c1.y); s  = fmaf(fmaxf(x, 0.f), ww[1].y, s);
                x = fmaf(dj, uu[1].z, a1.z + c1.z); s  = fmaf(fmaxf(x, 0.f), ww[1].z, s);
                x = fmaf(dj, uu[1].w, a1.w + c1.w); s  = fmaf(fmaxf(x, 0.f), ww[1].w, s);
                x = fmaf(dj, uu[2].x, a2.x + c2.x); s  = fmaf(fmaxf(x, 0.f), ww[2].x, s);
                x = fmaf(dj, uu[2].y, a2.y + c2.y); s  = fmaf(fmaxf(x, 0.f), ww[2].y, s);
                x = fmaf(dj, uu[2].z, a2.z + c2.z); s  = fmaf(fmaxf(x, 0.f), ww[2].z, s);
                x = fmaf(dj, uu[2].w, a2.w + c2.w); s  = fmaf(fmaxf(x, 0.f), ww[2].w, s);
            }
            // reduce within each 16-lane half
            s += __shfl_xor_sync(0xffffffffu, s, 8);
            s += __shfl_xor_sync(0xffffffffu, s, 4);
            s += __shfl_xor_sync(0xffffffffu, s, 2);
            s += __shfl_xor_sync(0xffffffffu, s, 1);
            if (lane16 == 0 && j + half < cnt) out[base + j + half] = s + b2v;
        }
    }
}

// ---------------------------------------------------------------------------
extern "C" void kernel_launch(void* const* d_in, const int* in_sizes, int n_in,
                              void* d_out, int out_size)
{
    const int*   z        = (const int*)  d_in[1];
    const float* pos      = (const float*)d_in[2];
    const float* emb      = (const float*)d_in[5];
    const float* layer_W  = (const float*)d_in[6];
    const float* layer_b  = (const float*)d_in[7];
    const float* layer_g  = (const float*)d_in[8];
    const float* layer_bt = (const float*)d_in[9];
    const float* dist_W   = (const float*)d_in[10];
    const float* dist_b   = (const float*)d_in[11];
    const float* head_W1  = (const float*)d_in[12];
    const float* head_b1  = (const float*)d_in[13];
    const float* head_W2  = (const float*)d_in[14];
    const float* head_b2  = (const float*)d_in[15];
    float* out = (float*)d_out;

    const int B   = out_size;                // molecules
    const int N   = in_sizes[1];             // atoms
    const int nz  = in_sizes[5] / H;         // embedding rows (104)
    const int L   = in_sizes[6] / (H * H);   // layers (5)
    const int apm = N / B;                   // atoms per molecule (uniform)

    // 0) transpose weights (64x64 tiles) + u/v
    transpose_kernel<<<dim3(3, 3, L + 4), 256>>>(layer_W, head_W1,
                                                 dist_W, dist_b, head_b1, L);
    // 1) tower + P1'(+v)/P2 tables
    prep_kernel<<<nz, 192>>>(emb, layer_b, layer_g, layer_bt, L);
    // 2) per-molecule output (2 molecules per warp-iteration)
    final_kernel<<<148 * 4, 256>>>(z, pos, head_W2, head_b2, out, B, apm);
}